// round 6
// baseline (speedup 1.0000x reference)
#include <cuda_runtime.h>
#include <cuda_bf16.h>
#include <math.h>

#define BATCH 4096
#define DIM 1024
#define NG 1024
#define NSPLIT 64            // column splits of 64 (per warp-column)
#define TEMP_INV 10.0f

// ---------------- scratch ----------------------------------------------------
__device__ __align__(16) unsigned short g_qh[BATCH * DIM];
__device__ __align__(16) unsigned short g_ql[BATCH * DIM];
__device__ __align__(16) unsigned short g_ah[BATCH * DIM];
__device__ __align__(16) unsigned short g_al[BATCH * DIM];

__device__ int    g_smax[NG];
__device__ int    g_smin[NG];
__device__ float  g_wsum[NG];
__device__ float  g_w[BATCH];
__device__ float  g_pm[BATCH * NSPLIT];
__device__ float  g_ps[BATCH * NSPLIT];
__device__ float  g_pmaxv[BATCH * NSPLIT];
__device__ int    g_pmaxj[BATCH * NSPLIT];
__device__ float  g_pdot[BATCH * NSPLIT];
__device__ float  g_pwr[BATCH * NSPLIT];
__device__ double g_loss;
__device__ int    g_acc;

// ---------------- PTX helpers -------------------------------------------------
__device__ __forceinline__ unsigned smem_u32(const void* p) {
    unsigned a;
    asm("{ .reg .u64 t; cvta.to.shared.u64 t, %1; cvt.u32.u64 %0, t; }" : "=r"(a) : "l"(p));
    return a;
}

__device__ __forceinline__ void cp16(unsigned dst, const void* src) {
    asm volatile("cp.async.cg.shared.global [%0], [%1], 16;" :: "r"(dst), "l"(src) : "memory");
}
__device__ __forceinline__ void cp_commit() {
    asm volatile("cp.async.commit_group;" ::: "memory");
}
template <int N>
__device__ __forceinline__ void cp_wait() {
    asm volatile("cp.async.wait_group %0;" :: "n"(N) : "memory");
}

__device__ __forceinline__ void ldsm4(unsigned& r0, unsigned& r1, unsigned& r2, unsigned& r3,
                                      unsigned addr) {
    asm volatile("ldmatrix.sync.aligned.m8n8.x4.shared.b16 {%0,%1,%2,%3}, [%4];"
        : "=r"(r0), "=r"(r1), "=r"(r2), "=r"(r3) : "r"(addr));
}

__device__ __forceinline__ void mma_bf16(float* c, unsigned a0, unsigned a1, unsigned a2,
                                         unsigned a3, unsigned b0, unsigned b1) {
    asm volatile(
        "mma.sync.aligned.m16n8k16.row.col.f32.bf16.bf16.f32 "
        "{%0,%1,%2,%3}, {%4,%5,%6,%7}, {%8,%9}, {%0,%1,%2,%3};"
        : "+f"(c[0]), "+f"(c[1]), "+f"(c[2]), "+f"(c[3])
        : "r"(a0), "r"(a1), "r"(a2), "r"(a3), "r"(b0), "r"(b1));
}

// ---------------- weight prep -------------------------------------------------
__global__ void k_init() {
    int i = blockIdx.x * blockDim.x + threadIdx.x;
    if (i < NG) {
        g_smax[i] = 0xFF800000;
        g_smin[i] = 0x7F800000;
        g_wsum[i] = 0.0f;
    }
    if (i == 0) { g_loss = 0.0; g_acc = 0; }
}

__global__ void k_minmax(const float* __restrict__ scores, const int* __restrict__ qid) {
    int i = blockIdx.x * blockDim.x + threadIdx.x;
    if (i >= BATCH) return;
    int b = __float_as_int(scores[i]);
    int g = qid[i];
    atomicMax(&g_smax[g], b);
    atomicMin(&g_smin[g], b);
}

__global__ void k_weight(const float* __restrict__ scores, const float* __restrict__ ranks,
                         const int* __restrict__ qid) {
    int i = blockIdx.x * blockDim.x + threadIdx.x;
    if (i >= BATCH) return;
    int g = qid[i];
    float w = expf(-0.1f * ranks[i]);
    float mx = __int_as_float(g_smax[g]);
    float mn = __int_as_float(g_smin[g]);
    float den = mx - mn;
    float norm = (den > 0.0f) ? (scores[i] - mn) / den : 0.0f;
    w *= expf(0.01f * norm);
    g_w[i] = w;
    atomicAdd(&g_wsum[g], w);
}

__global__ void k_wnorm(const int* __restrict__ qid) {
    int i = blockIdx.x * blockDim.x + threadIdx.x;
    if (i >= BATCH) return;
    g_w[i] = g_w[i] / g_wsum[qid[i]];
}

// ---------------- fp32 -> bf16 hi/lo (row-major) ------------------------------
__global__ void k_convert(const float* __restrict__ Q, const float* __restrict__ A) {
    int idx = blockIdx.x * blockDim.x + threadIdx.x;   // 0 .. 524287
    const float* src = (blockIdx.y == 0) ? Q : A;
    unsigned short* dh = (blockIdx.y == 0) ? g_qh : g_ah;
    unsigned short* dl = (blockIdx.y == 0) ? g_ql : g_al;

    size_t e0 = (size_t)idx * 8;
    float4 f0 = *(const float4*)(src + e0);
    float4 f1 = *(const float4*)(src + e0 + 4);
    float v[8] = {f0.x, f0.y, f0.z, f0.w, f1.x, f1.y, f1.z, f1.w};

    unsigned short hs[8], ls[8];
#pragma unroll
    for (int i = 0; i < 8; i++) {
        __nv_bfloat16 h = __float2bfloat16(v[i]);
        float hf = __bfloat162float(h);
        __nv_bfloat16 l = __float2bfloat16(v[i] - hf);
        hs[i] = __bfloat16_as_ushort(h);
        ls[i] = __bfloat16_as_ushort(l);
    }
    uint4 hp, lp;
    hp.x = (unsigned)hs[0] | ((unsigned)hs[1] << 16);
    hp.y = (unsigned)hs[2] | ((unsigned)hs[3] << 16);
    hp.z = (unsigned)hs[4] | ((unsigned)hs[5] << 16);
    hp.w = (unsigned)hs[6] | ((unsigned)hs[7] << 16);
    lp.x = (unsigned)ls[0] | ((unsigned)ls[1] << 16);
    lp.y = (unsigned)ls[2] | ((unsigned)ls[3] << 16);
    lp.z = (unsigned)ls[4] | ((unsigned)ls[5] << 16);
    lp.w = (unsigned)ls[6] | ((unsigned)ls[7] << 16);
    *(uint4*)(dh + e0) = hp;
    *(uint4*)(dl + e0) = lp;
}

// ---------------- main: bf16-split mma.sync GEMM + fused epilogue -------------
// Grid (32, 32): CTA tile rows [bx*128,+128) x cols [by*128,+128).
// 8 warps as 4(m) x 2(n); warp tile 32 x 64. BK = 32.
// smem: sq[128] int @0, sw[128] float @512, stages @1024: 2 x (4 tiles x 10240B)
#define TILE_B  10240u            // 128 rows x 40 halfs x 2B (stride 40 for LDSM + cp16 align)
#define STG_OFF 1024u
#define STG_SZ  (4u * TILE_B)     // 40960
#define SMEM_TOTAL (1024 + 2 * 40960)

__global__ void __launch_bounds__(256, 2) k_mma(const int* __restrict__ qid) {
    extern __shared__ char smem[];
    const unsigned sb = smem_u32(smem);
    const int tid = threadIdx.x;
    const int wid = tid >> 5;
    const int lid = tid & 31;
    const int wm = wid & 3;        // m warp 0..3
    const int wn = wid >> 2;       // n warp 0..1
    const int bx = blockIdx.x, by = blockIdx.y;

    // column tables
    if (tid < 128) {
        int c = by * 128 + tid;
        ((int*)(smem))[tid] = qid[c];
        ((float*)(smem + 512))[tid] = g_w[c];
    }

    float acc[2][8][4];
#pragma unroll
    for (int i = 0; i < 2; i++)
#pragma unroll
        for (int j = 0; j < 8; j++)
#pragma unroll
            for (int k = 0; k < 4; k++) acc[i][j][k] = 0.0f;

    // ---- async load of one k-chunk into stage buf ---------------------------
    auto load_chunk = [&](int kc, int buf) {
        unsigned stg = sb + STG_OFF + buf * STG_SZ;
#pragma unroll
        for (int c8 = 0; c8 < 8; c8++) {
            int c = tid + c8 * 256;          // 0..2047
            int tile = c >> 9;               // 0..3: qh, ql, ah, al
            int row = (c >> 2) & 127;
            int j = c & 3;
            const unsigned short* base =
                (tile == 0) ? g_qh : (tile == 1) ? g_ql : (tile == 2) ? g_ah : g_al;
            int grow = ((tile < 2) ? bx : by) * 128 + row;
            const unsigned short* src = base + (size_t)grow * DIM + kc * 32 + 8 * j;
            unsigned dst = stg + tile * TILE_B + row * 80 + 16 * j;
            cp16(dst, src);
        }
        cp_commit();
    };

    // A-fragment lane address pieces (row-major m16 x k16 via x4)
    const int a_r = (lid & 15);
    const int a_k = (lid >> 4) << 3;
    // B-fragment lane address pieces (two n8 tiles per x4)
    const int b_n = ((lid >> 4) << 3) + (lid & 7);
    const int b_k = ((lid >> 3) & 1) << 3;

    load_chunk(0, 0);

    for (int kc = 0; kc < 32; kc++) {
        cp_wait<0>();
        __syncthreads();      // stage kc fully visible; prior-iter readers done
        if (kc < 31) load_chunk(kc + 1, (kc + 1) & 1);   // safe: buffer's readers passed the barrier

        unsigned stg = sb + STG_OFF + (kc & 1) * STG_SZ;
        unsigned qhb = stg + 0 * TILE_B;
        unsigned qlb = stg + 1 * TILE_B;
        unsigned ahb = stg + 2 * TILE_B;
        unsigned alb = stg + 3 * TILE_B;

#pragma unroll
        for (int ks = 0; ks < 2; ks++) {
            const int ko = ks * 16;
            unsigned a[2][4], bh[4][4], bl[4][4];
            // Qh A-frags
#pragma unroll
            for (int mt = 0; mt < 2; mt++) {
                unsigned ad = qhb + (wm * 32 + mt * 16 + a_r) * 80 + (ko + a_k) * 2;
                ldsm4(a[mt][0], a[mt][1], a[mt][2], a[mt][3], ad);
            }
            // Ah B-frags
#pragma unroll
            for (int p = 0; p < 4; p++) {
                unsigned ad = ahb + (wn * 64 + p * 16 + b_n) * 80 + (ko + b_k) * 2;
                ldsm4(bh[p][0], bh[p][1], bh[p][2], bh[p][3], ad);
            }
            // Qh . Ah
#pragma unroll
            for (int mt = 0; mt < 2; mt++)
#pragma unroll
                for (int p = 0; p < 4; p++) {
                    mma_bf16(acc[mt][2 * p],     a[mt][0], a[mt][1], a[mt][2], a[mt][3], bh[p][0], bh[p][1]);
                    mma_bf16(acc[mt][2 * p + 1], a[mt][0], a[mt][1], a[mt][2], a[mt][3], bh[p][2], bh[p][3]);
                }
            // Al B-frags, Qh . Al
#pragma unroll
            for (int p = 0; p < 4; p++) {
                unsigned ad = alb + (wn * 64 + p * 16 + b_n) * 80 + (ko + b_k) * 2;
                ldsm4(bl[p][0], bl[p][1], bl[p][2], bl[p][3], ad);
            }
#pragma unroll
            for (int mt = 0; mt < 2; mt++)
#pragma unroll
                for (int p = 0; p < 4; p++) {
                    mma_bf16(acc[mt][2 * p],     a[mt][0], a[mt][1], a[mt][2], a[mt][3], bl[p][0], bl[p][1]);
                    mma_bf16(acc[mt][2 * p + 1], a[mt][0], a[mt][1], a[mt][2], a[mt][3], bl[p][2], bl[p][3]);
                }
            // Ql A-frags, Ql . Ah
#pragma unroll
            for (int mt = 0; mt < 2; mt++) {
                unsigned ad = qlb + (wm * 32 + mt * 16 + a_r) * 80 + (ko + a_k) * 2;
                ldsm4(a[mt][0], a[mt][1], a[mt][2], a[mt][3], ad);
            }
#pragma unroll
            for (int mt = 0; mt < 2; mt++)
#pragma unroll
                for (int p = 0; p < 4; p++) {
                    mma_bf16(acc[mt][2 * p],     a[mt][0], a[mt][1], a[mt][2], a[mt][3], bh[p][0], bh[p][1]);
                    mma_bf16(acc[mt][2 * p + 1], a[mt][0], a[mt][1], a[mt][2], a[mt][3], bh[p][2], bh[p][3]);
                }
        }
    }

    // ---- fused epilogue -----------------------------------------------------
    const int* sq = (const int*)(smem);
    const float* swt = (const float*)(smem + 512);
    const unsigned fullm = 0xffffffffu;

#pragma unroll
    for (int mt = 0; mt < 2; mt++) {
#pragma unroll
        for (int h = 0; h < 2; h++) {
            int row = bx * 128 + wm * 32 + mt * 16 + h * 8 + (lid >> 2);
            int rq = qid[row];
            float m = -1e30f, s = 0.0f, mv = -1e30f, dot = 0.0f, wr = 0.0f;
            int mj = 0;
#pragma unroll
            for (int nt = 0; nt < 8; nt++) {
#pragma unroll
                for (int b = 0; b < 2; b++) {
                    float val = acc[mt][nt][2 * h + b] * TEMP_INV;
                    int cl = wn * 64 + nt * 8 + 2 * (lid & 3) + b;
                    if (val > m) {
                        s = s * __expf(m - val) + 1.0f;
                        m = val;
                    } else {
                        s += __expf(val - m);
                    }
                    if (val > mv) { mv = val; mj = by * 128 + cl; }
                    if (sq[cl] == rq) {
                        float wj = swt[cl];
                        dot = fmaf(wj, val, dot);
                        wr += wj;
                    }
                }
            }
            // reduce across the 4 lanes owning this row (lanes 4k..4k+3)
#pragma unroll
            for (int off = 2; off > 0; off >>= 1) {
                float om  = __shfl_down_sync(fullm, m, off, 4);
                float os  = __shfl_down_sync(fullm, s, off, 4);
                float omv = __shfl_down_sync(fullm, mv, off, 4);
                int   oj  = __shfl_down_sync(fullm, mj, off, 4);
                float od  = __shfl_down_sync(fullm, dot, off, 4);
                float ow  = __shfl_down_sync(fullm, wr, off, 4);
                float M = fmaxf(m, om);
                s = s * __expf(m - M) + os * __expf(om - M);
                m = M;
                if (omv > mv || (omv == mv && oj < mj)) { mv = omv; mj = oj; }
                dot += od;
                wr += ow;
            }
            if ((lid & 3) == 0) {
                int pidx = row * NSPLIT + (by * 2 + wn);
                g_pm[pidx] = m; g_ps[pidx] = s;
                g_pmaxv[pidx] = mv; g_pmaxj[pidx] = mj;
                g_pdot[pidx] = dot; g_pwr[pidx] = wr;
            }
        }
    }
}

// ---------------- merge splits ------------------------------------------------
__global__ void k_merge(const int* __restrict__ qid) {
    int row = blockIdx.x * blockDim.x + threadIdx.x;
    if (row >= BATCH) return;
    float m = -1e30f, s = 0.0f, mv = -1e30f, dot = 0.0f, wr = 0.0f;
    int mj = 0;
    for (int p = 0; p < NSPLIT; p++) {
        int idx = row * NSPLIT + p;
        float om = g_pm[idx], os = g_ps[idx];
        float M = fmaxf(m, om);
        s = s * __expf(m - M) + os * __expf(om - M);
        m = M;
        float omv = g_pmaxv[idx];
        int oj = g_pmaxj[idx];
        if (omv > mv || (omv == mv && oj < mj)) { mv = omv; mj = oj; }
        dot += g_pdot[idx];
        wr += g_pwr[idx];
    }
    float lse = m + logf(s);
    float per_row = wr * lse - dot;
    int ok = (qid[mj] == qid[row]) ? 1 : 0;
    atomicAdd(&g_loss, (double)per_row);
    atomicAdd(&g_acc, ok);
}

__global__ void k_final(float* __restrict__ out, int out_size) {
    if (threadIdx.x == 0) {
        if (out_size > 0) out[0] = (float)(g_loss / (double)BATCH);
        if (out_size > 1) out[1] = (float)g_acc / (float)BATCH;
    }
}

// ---------------- launch -------------------------------------------------------
extern "C" void kernel_launch(void* const* d_in, const int* in_sizes, int n_in,
                              void* d_out, int out_size) {
    const float* Q      = (const float*)d_in[0];
    const float* A      = (const float*)d_in[1];
    const int*   qid    = (const int*)d_in[2];
    const float* ranks  = (const float*)d_in[3];
    const float* scores = (const float*)d_in[4];
    float* out = (float*)d_out;

    cudaFuncSetAttribute(k_mma, cudaFuncAttributeMaxDynamicSharedMemorySize, SMEM_TOTAL);

    k_init<<<(NG + 255) / 256, 256>>>();
    k_minmax<<<(BATCH + 255) / 256, 256>>>(scores, qid);
    k_weight<<<(BATCH + 255) / 256, 256>>>(scores, ranks, qid);
    k_wnorm<<<(BATCH + 255) / 256, 256>>>(qid);
    k_convert<<<dim3(2048, 2), 256>>>(Q, A);
    k_mma<<<dim3(32, 32), 256, SMEM_TOTAL>>>(qid);
    k_merge<<<(BATCH + 255) / 256, 256>>>(qid);
    k_final<<<1, 32>>>(out, out_size);
}

// round 7
// speedup vs baseline: 1.3725x; 1.3725x over previous
#include <cuda_runtime.h>
#include <cuda_bf16.h>
#include <math.h>

#define BATCH 4096
#define DIM 1024
#define NG 1024
#define NSPLIT 64            // column splits of 64 (per warp-column)
#define TEMP_INV 10.0f

// ---------------- scratch ----------------------------------------------------
__device__ __align__(16) unsigned short g_qh[BATCH * DIM];
__device__ __align__(16) unsigned short g_ql[BATCH * DIM];
__device__ __align__(16) unsigned short g_ah[BATCH * DIM];
__device__ __align__(16) unsigned short g_al[BATCH * DIM];

__device__ int    g_smax[NG];
__device__ int    g_smin[NG];
__device__ float  g_wsum[NG];
__device__ float  g_w[BATCH];
__device__ float  g_pm[BATCH * NSPLIT];
__device__ float  g_ps[BATCH * NSPLIT];
__device__ float  g_pmaxv[BATCH * NSPLIT];
__device__ int    g_pmaxj[BATCH * NSPLIT];
__device__ float  g_pdot[BATCH * NSPLIT];
__device__ float  g_pwr[BATCH * NSPLIT];
__device__ double g_loss;
__device__ int    g_acc;

// ---------------- PTX helpers -------------------------------------------------
__device__ __forceinline__ unsigned smem_u32(const void* p) {
    unsigned a;
    asm("{ .reg .u64 t; cvta.to.shared.u64 t, %1; cvt.u32.u64 %0, t; }" : "=r"(a) : "l"(p));
    return a;
}

__device__ __forceinline__ void cp16(unsigned dst, const void* src) {
    asm volatile("cp.async.cg.shared.global [%0], [%1], 16;" :: "r"(dst), "l"(src) : "memory");
}
__device__ __forceinline__ void cp_commit() {
    asm volatile("cp.async.commit_group;" ::: "memory");
}
template <int N>
__device__ __forceinline__ void cp_wait() {
    asm volatile("cp.async.wait_group %0;" :: "n"(N) : "memory");
}

__device__ __forceinline__ void ldsm4(unsigned& r0, unsigned& r1, unsigned& r2, unsigned& r3,
                                      unsigned addr) {
    asm volatile("ldmatrix.sync.aligned.m8n8.x4.shared.b16 {%0,%1,%2,%3}, [%4];"
        : "=r"(r0), "=r"(r1), "=r"(r2), "=r"(r3) : "r"(addr));
}

__device__ __forceinline__ void mma_bf16(float* c, unsigned a0, unsigned a1, unsigned a2,
                                         unsigned a3, unsigned b0, unsigned b1) {
    asm volatile(
        "mma.sync.aligned.m16n8k16.row.col.f32.bf16.bf16.f32 "
        "{%0,%1,%2,%3}, {%4,%5,%6,%7}, {%8,%9}, {%0,%1,%2,%3};"
        : "+f"(c[0]), "+f"(c[1]), "+f"(c[2]), "+f"(c[3])
        : "r"(a0), "r"(a1), "r"(a2), "r"(a3), "r"(b0), "r"(b1));
}

// ---------------- weight prep -------------------------------------------------
__global__ void k_init() {
    int i = blockIdx.x * blockDim.x + threadIdx.x;
    if (i < NG) {
        g_smax[i] = 0xFF800000;
        g_smin[i] = 0x7F800000;
        g_wsum[i] = 0.0f;
    }
    if (i == 0) { g_loss = 0.0; g_acc = 0; }
}

__global__ void k_minmax(const float* __restrict__ scores, const int* __restrict__ qid) {
    int i = blockIdx.x * blockDim.x + threadIdx.x;
    if (i >= BATCH) return;
    int b = __float_as_int(scores[i]);
    int g = qid[i];
    atomicMax(&g_smax[g], b);
    atomicMin(&g_smin[g], b);
}

__global__ void k_weight(const float* __restrict__ scores, const float* __restrict__ ranks,
                         const int* __restrict__ qid) {
    int i = blockIdx.x * blockDim.x + threadIdx.x;
    if (i >= BATCH) return;
    int g = qid[i];
    float w = expf(-0.1f * ranks[i]);
    float mx = __int_as_float(g_smax[g]);
    float mn = __int_as_float(g_smin[g]);
    float den = mx - mn;
    float norm = (den > 0.0f) ? (scores[i] - mn) / den : 0.0f;
    w *= expf(0.01f * norm);
    g_w[i] = w;
    atomicAdd(&g_wsum[g], w);
}

__global__ void k_wnorm(const int* __restrict__ qid) {
    int i = blockIdx.x * blockDim.x + threadIdx.x;
    if (i >= BATCH) return;
    g_w[i] = g_w[i] / g_wsum[qid[i]];
}

// ---------------- fp32 -> bf16 hi/lo (row-major) ------------------------------
__global__ void k_convert(const float* __restrict__ Q, const float* __restrict__ A) {
    int idx = blockIdx.x * blockDim.x + threadIdx.x;   // 0 .. 524287
    const float* src = (blockIdx.y == 0) ? Q : A;
    unsigned short* dh = (blockIdx.y == 0) ? g_qh : g_ah;
    unsigned short* dl = (blockIdx.y == 0) ? g_ql : g_al;

    size_t e0 = (size_t)idx * 8;
    float4 f0 = *(const float4*)(src + e0);
    float4 f1 = *(const float4*)(src + e0 + 4);
    float v[8] = {f0.x, f0.y, f0.z, f0.w, f1.x, f1.y, f1.z, f1.w};

    unsigned short hs[8], ls[8];
#pragma unroll
    for (int i = 0; i < 8; i++) {
        __nv_bfloat16 h = __float2bfloat16(v[i]);
        float hf = __bfloat162float(h);
        __nv_bfloat16 l = __float2bfloat16(v[i] - hf);
        hs[i] = __bfloat16_as_ushort(h);
        ls[i] = __bfloat16_as_ushort(l);
    }
    uint4 hp, lp;
    hp.x = (unsigned)hs[0] | ((unsigned)hs[1] << 16);
    hp.y = (unsigned)hs[2] | ((unsigned)hs[3] << 16);
    hp.z = (unsigned)hs[4] | ((unsigned)hs[5] << 16);
    hp.w = (unsigned)hs[6] | ((unsigned)hs[7] << 16);
    lp.x = (unsigned)ls[0] | ((unsigned)ls[1] << 16);
    lp.y = (unsigned)ls[2] | ((unsigned)ls[3] << 16);
    lp.z = (unsigned)ls[4] | ((unsigned)ls[5] << 16);
    lp.w = (unsigned)ls[6] | ((unsigned)ls[7] << 16);
    *(uint4*)(dh + e0) = hp;
    *(uint4*)(dl + e0) = lp;
}

// ---------------- main: bf16-split mma.sync GEMM + fused epilogue -------------
// Grid (32, 32): CTA tile rows [bx*128,+128) x cols [by*128,+128).
// 8 warps as 4(m) x 2(n); warp tile 32 x 64. BK = 32. 4-stage cp.async pipeline.
// smem: sq[128] int @0, sw[128] float @512, stages @1024: 4 x (4 tiles x 10240B)
#define TILE_B  10240u            // 128 rows x 40 halfs x 2B (stride 40 for LDSM + cp16 align)
#define STG_OFF 1024u
#define STG_SZ  (4u * TILE_B)     // 40960
#define NSTAGE  4
#define SMEM_TOTAL (1024 + NSTAGE * 40960)

__global__ void __launch_bounds__(256) k_mma(const int* __restrict__ qid) {
    extern __shared__ char smem[];
    const unsigned sb = smem_u32(smem);
    const int tid = threadIdx.x;
    const int wid = tid >> 5;
    const int lid = tid & 31;
    const int wm = wid & 3;        // m warp 0..3
    const int wn = wid >> 2;       // n warp 0..1
    const int bx = blockIdx.x, by = blockIdx.y;

    // column tables
    if (tid < 128) {
        int c = by * 128 + tid;
        ((int*)(smem))[tid] = qid[c];
        ((float*)(smem + 512))[tid] = g_w[c];
    }

    float acc[2][8][4];
#pragma unroll
    for (int i = 0; i < 2; i++)
#pragma unroll
        for (int j = 0; j < 8; j++)
#pragma unroll
            for (int k = 0; k < 4; k++) acc[i][j][k] = 0.0f;

    // ---- async load of one k-chunk into stage buf; empty commit past the end
    auto load_chunk = [&](int kc) {
        if (kc < 32) {
            unsigned stg = sb + STG_OFF + (unsigned)(kc & (NSTAGE - 1)) * STG_SZ;
#pragma unroll
            for (int c8 = 0; c8 < 8; c8++) {
                int c = tid + c8 * 256;          // 0..2047
                int tile = c >> 9;               // 0..3: qh, ql, ah, al
                int row = (c >> 2) & 127;
                int j = c & 3;
                const unsigned short* base =
                    (tile == 0) ? g_qh : (tile == 1) ? g_ql : (tile == 2) ? g_ah : g_al;
                int grow = ((tile < 2) ? bx : by) * 128 + row;
                const unsigned short* src = base + (size_t)grow * DIM + kc * 32 + 8 * j;
                unsigned dst = stg + tile * TILE_B + row * 80 + 16 * j;
                cp16(dst, src);
            }
        }
        cp_commit();   // constant group count, even past the end
    };

    // A-fragment lane address pieces (row-major m16 x k16 via x4)
    const int a_r = (lid & 15);
    const int a_k = (lid >> 4) << 3;
    // B-fragment lane address pieces (two n8 tiles per x4)
    const int b_n = ((lid >> 4) << 3) + (lid & 7);
    const int b_k = ((lid >> 3) & 1) << 3;

    load_chunk(0);
    load_chunk(1);
    load_chunk(2);

    for (int kc = 0; kc < 32; kc++) {
        cp_wait<2>();         // chunk kc's own stores complete (FIFO: kc+1,kc+2 may pend)
        __syncthreads();      // cross-thread visibility of chunk kc; frees buf (kc+3)%4
        load_chunk(kc + 3);   // prefetch 3 ahead (empty commit past end)

        unsigned stg = sb + STG_OFF + (unsigned)(kc & (NSTAGE - 1)) * STG_SZ;
        unsigned qhb = stg + 0 * TILE_B;
        unsigned qlb = stg + 1 * TILE_B;
        unsigned ahb = stg + 2 * TILE_B;
        unsigned alb = stg + 3 * TILE_B;

#pragma unroll
        for (int ks = 0; ks < 2; ks++) {
            const int ko = ks * 16;
            unsigned a[2][4], bh[4][4], bl[4][4];
            // Qh A-frags
#pragma unroll
            for (int mt = 0; mt < 2; mt++) {
                unsigned ad = qhb + (wm * 32 + mt * 16 + a_r) * 80 + (ko + a_k) * 2;
                ldsm4(a[mt][0], a[mt][1], a[mt][2], a[mt][3], ad);
            }
            // Ah B-frags
#pragma unroll
            for (int p = 0; p < 4; p++) {
                unsigned ad = ahb + (wn * 64 + p * 16 + b_n) * 80 + (ko + b_k) * 2;
                ldsm4(bh[p][0], bh[p][1], bh[p][2], bh[p][3], ad);
            }
            // Qh . Ah
#pragma unroll
            for (int mt = 0; mt < 2; mt++)
#pragma unroll
                for (int p = 0; p < 4; p++) {
                    mma_bf16(acc[mt][2 * p],     a[mt][0], a[mt][1], a[mt][2], a[mt][3], bh[p][0], bh[p][1]);
                    mma_bf16(acc[mt][2 * p + 1], a[mt][0], a[mt][1], a[mt][2], a[mt][3], bh[p][2], bh[p][3]);
                }
            // Al B-frags, Qh . Al
#pragma unroll
            for (int p = 0; p < 4; p++) {
                unsigned ad = alb + (wn * 64 + p * 16 + b_n) * 80 + (ko + b_k) * 2;
                ldsm4(bl[p][0], bl[p][1], bl[p][2], bl[p][3], ad);
            }
#pragma unroll
            for (int mt = 0; mt < 2; mt++)
#pragma unroll
                for (int p = 0; p < 4; p++) {
                    mma_bf16(acc[mt][2 * p],     a[mt][0], a[mt][1], a[mt][2], a[mt][3], bl[p][0], bl[p][1]);
                    mma_bf16(acc[mt][2 * p + 1], a[mt][0], a[mt][1], a[mt][2], a[mt][3], bl[p][2], bl[p][3]);
                }
            // Ql A-frags, Ql . Ah
#pragma unroll
            for (int mt = 0; mt < 2; mt++) {
                unsigned ad = qlb + (wm * 32 + mt * 16 + a_r) * 80 + (ko + a_k) * 2;
                ldsm4(a[mt][0], a[mt][1], a[mt][2], a[mt][3], ad);
            }
#pragma unroll
            for (int mt = 0; mt < 2; mt++)
#pragma unroll
                for (int p = 0; p < 4; p++) {
                    mma_bf16(acc[mt][2 * p],     a[mt][0], a[mt][1], a[mt][2], a[mt][3], bh[p][0], bh[p][1]);
                    mma_bf16(acc[mt][2 * p + 1], a[mt][0], a[mt][1], a[mt][2], a[mt][3], bh[p][2], bh[p][3]);
                }
        }
    }

    // ---- fused epilogue -----------------------------------------------------
    const int* sq = (const int*)(smem);
    const float* swt = (const float*)(smem + 512);
    const unsigned fullm = 0xffffffffu;

#pragma unroll
    for (int mt = 0; mt < 2; mt++) {
#pragma unroll
        for (int h = 0; h < 2; h++) {
            int row = bx * 128 + wm * 32 + mt * 16 + h * 8 + (lid >> 2);
            int rq = qid[row];
            float m = -1e30f, s = 0.0f, mv = -1e30f, dot = 0.0f, wr = 0.0f;
            int mj = 0;
#pragma unroll
            for (int nt = 0; nt < 8; nt++) {
#pragma unroll
                for (int b = 0; b < 2; b++) {
                    float val = acc[mt][nt][2 * h + b] * TEMP_INV;
                    int cl = wn * 64 + nt * 8 + 2 * (lid & 3) + b;
                    if (val > m) {
                        s = s * __expf(m - val) + 1.0f;
                        m = val;
                    } else {
                        s += __expf(val - m);
                    }
                    if (val > mv) { mv = val; mj = by * 128 + cl; }
                    if (sq[cl] == rq) {
                        float wj = swt[cl];
                        dot = fmaf(wj, val, dot);
                        wr += wj;
                    }
                }
            }
            // reduce across the 4 lanes owning this row (lanes 4k..4k+3)
#pragma unroll
            for (int off = 2; off > 0; off >>= 1) {
                float om  = __shfl_down_sync(fullm, m, off, 4);
                float os  = __shfl_down_sync(fullm, s, off, 4);
                float omv = __shfl_down_sync(fullm, mv, off, 4);
                int   oj  = __shfl_down_sync(fullm, mj, off, 4);
                float od  = __shfl_down_sync(fullm, dot, off, 4);
                float ow  = __shfl_down_sync(fullm, wr, off, 4);
                float M = fmaxf(m, om);
                s = s * __expf(m - M) + os * __expf(om - M);
                m = M;
                if (omv > mv || (omv == mv && oj < mj)) { mv = omv; mj = oj; }
                dot += od;
                wr += ow;
            }
            if ((lid & 3) == 0) {
                int pidx = row * NSPLIT + (by * 2 + wn);
                g_pm[pidx] = m; g_ps[pidx] = s;
                g_pmaxv[pidx] = mv; g_pmaxj[pidx] = mj;
                g_pdot[pidx] = dot; g_pwr[pidx] = wr;
            }
        }
    }
}

// ---------------- merge splits ------------------------------------------------
__global__ void k_merge(const int* __restrict__ qid) {
    int row = blockIdx.x * blockDim.x + threadIdx.x;
    if (row >= BATCH) return;
    float m = -1e30f, s = 0.0f, mv = -1e30f, dot = 0.0f, wr = 0.0f;
    int mj = 0;
    for (int p = 0; p < NSPLIT; p++) {
        int idx = row * NSPLIT + p;
        float om = g_pm[idx], os = g_ps[idx];
        float M = fmaxf(m, om);
        s = s * __expf(m - M) + os * __expf(om - M);
        m = M;
        float omv = g_pmaxv[idx];
        int oj = g_pmaxj[idx];
        if (omv > mv || (omv == mv && oj < mj)) { mv = omv; mj = oj; }
        dot += g_pdot[idx];
        wr += g_pwr[idx];
    }
    float lse = m + logf(s);
    float per_row = wr * lse - dot;
    int ok = (qid[mj] == qid[row]) ? 1 : 0;
    atomicAdd(&g_loss, (double)per_row);
    atomicAdd(&g_acc, ok);
}

__global__ void k_final(float* __restrict__ out, int out_size) {
    if (threadIdx.x == 0) {
        if (out_size > 0) out[0] = (float)(g_loss / (double)BATCH);
        if (out_size > 1) out[1] = (float)g_acc / (float)BATCH;
    }
}

// ---------------- launch -------------------------------------------------------
extern "C" void kernel_launch(void* const* d_in, const int* in_sizes, int n_in,
                              void* d_out, int out_size) {
    const float* Q      = (const float*)d_in[0];
    const float* A      = (const float*)d_in[1];
    const int*   qid    = (const int*)d_in[2];
    const float* ranks  = (const float*)d_in[3];
    const float* scores = (const float*)d_in[4];
    float* out = (float*)d_out;

    cudaFuncSetAttribute(k_mma, cudaFuncAttributeMaxDynamicSharedMemorySize, SMEM_TOTAL);

    k_init<<<(NG + 255) / 256, 256>>>();
    k_minmax<<<(BATCH + 255) / 256, 256>>>(scores, qid);
    k_weight<<<(BATCH + 255) / 256, 256>>>(scores, ranks, qid);
    k_wnorm<<<(BATCH + 255) / 256, 256>>>(qid);
    k_convert<<<dim3(2048, 2), 256>>>(Q, A);
    k_mma<<<dim3(32, 32), 256, SMEM_TOTAL>>>(qid);
    k_merge<<<(BATCH + 255) / 256, 256>>>(qid);
    k_final<<<1, 32>>>(out, out_size);
}